// round 17
// baseline (speedup 1.0000x reference)
#include <cuda_runtime.h>
#include <cuda_bf16.h>
#include <math.h>
#include <stdint.h>

#define N_TOK   8192
#define D_DIM   4096
#define D2      (D_DIM / 2)                  // 2048 k-pairs
#define N_EXP   64
#define CAP     160                          // ceil(1.25*8192/64)
#define NEC     (N_TOK * N_EXP * CAP)        // 83,886,080
#define FLAT    (N_TOK * 2)                  // 16384

#define TILE_K  64
#define NT      (D_DIM / TILE_K)             // 64 tiles
#define GEMM_GRID (N_TOK / 64)               // 128 blocks, 64 tokens each

// zero-fill: each GEMM block owns 2*NEC/128 floats = 327,680 float4,
// spread over 64 tiles = 5120 float4/tile = 20 per thread.
#define ZBLK4   327680
#define ZTILE4  5120

// smem per buffer (u32 units): bf16-pair tiles, stride 36 (conflict-free frags)
#define XH_OFF  0                            // x hi   [64 rows][36]
#define XM_OFF  2304                         // x mid
#define GH_OFF  4608                         // gate hi [64 cols][36]
#define GM_OFF  6912                         // gate mid
#define BUF_U32 9216
#define SMEM_BYTES (2 * BUF_U32 * 4)         // 73,728
#define LG_S    68                           // logits overlay stride (f32)

// ---------------- device scratch ------------------------------------------
__device__ __align__(16) unsigned g_gate_h[N_EXP * D2];   // bf16x2 [e][kp]
__device__ __align__(16) unsigned g_gate_m[N_EXP * D2];   // bf16x2 [e][kp]
__device__ __align__(16) unsigned char g_top_idx8[FLAT];
__device__ __align__(16) float g_top_w[FLAT];
__device__ __align__(16) float g_psum[N_EXP];

#define MMA_BF16(c0, c1, c2, c3, a0, a1, a2, a3, b0, b1)                      \
    asm volatile(                                                             \
        "mma.sync.aligned.m16n8k16.row.col.f32.bf16.bf16.f32 "                \
        "{%0,%1,%2,%3}, {%4,%5,%6,%7}, {%8,%9}, {%0,%1,%2,%3};"               \
        : "+f"(c0), "+f"(c1), "+f"(c2), "+f"(c3)                              \
        : "r"(a0), "r"(a1), "r"(a2), "r"(a3), "r"(b0), "r"(b1))

__device__ __forceinline__ void bf16_split2(float v0, float v1,
                                            unsigned& h, unsigned& m) {
    __nv_bfloat162 h2 = __float22bfloat162_rn(make_float2(v0, v1));
    float2 hf = __bfloat1622float2(h2);
    __nv_bfloat162 m2 = __float22bfloat162_rn(make_float2(v0 - hf.x, v1 - hf.y));
    h = *(unsigned*)&h2;
    m = *(unsigned*)&m2;
}

// ---------------- prep: pack gate into bf16x2 hi/mid [e][kp] + init -------
__global__ void k_prep(const float* __restrict__ gate_w,
                       float* __restrict__ out_loss) {
    int idx = blockIdx.x * 256 + threadIdx.x;   // 0 .. E*D2-1
    int e  = idx >> 11;
    int kp = idx & (D2 - 1);
    float v0 = gate_w[(size_t)e * D_DIM + 2 * kp];
    float v1 = gate_w[(size_t)e * D_DIM + 2 * kp + 1];
    unsigned h, m;
    bf16_split2(v0, v1, h, m);
    g_gate_h[idx] = h;
    g_gate_m[idx] = m;
    if (blockIdx.x == 0) {
        if (threadIdx.x < N_EXP) g_psum[threadIdx.x] = 0.0f;
        if (threadIdx.x == 64) out_loss[0] = 0.0f;
    }
}

// ---------------- bf16 4-product GEMM + zero-fill + topk ------------------
__global__ void __launch_bounds__(256)
k_gemm(const float* __restrict__ x, const float* __restrict__ gate_w,
       float* __restrict__ probs_out,
       float4* __restrict__ zero_base /* mask+comb = 2*NEC floats */) {
    extern __shared__ unsigned sm[];
    __shared__ float smax[64], sinv[64];
    __shared__ float part[4][64];
    __shared__ float exlg[64];
    __shared__ int s_nf, s_list[64];

    const int tid  = threadIdx.x;
    const int wid  = tid >> 5;
    const int lane = tid & 31;
    const int n0   = blockIdx.x * 64;

    const int wm = (wid & 3) * 16;       // token offset within block tile
    const int wn = (wid >> 2) * 32;      // expert offset

    float c[4][4];
#pragma unroll
    for (int nt = 0; nt < 4; nt++)
#pragma unroll
        for (int j = 0; j < 4; j++) c[nt][j] = 0.0f;

    const int g  = lane >> 2;            // 0..7
    const int t4 = lane & 3;             // 0..3
    const unsigned abase = (unsigned)((wm + g) * 36 + t4);

    float4* zb = zero_base + (size_t)blockIdx.x * ZBLK4 + tid;
    const float4 z4 = make_float4(0.f, 0.f, 0.f, 0.f);

    // prefetch assignments
    const int pr = tid >> 4;             // x row 0..15 (stride 16 over l)
    const int pq = (tid & 15) * 4;       // x col group (4 k = 2 pairs)
    const int ge = tid >> 2;             // gate expert 0..63
    const int gq = (tid & 3) * 8;        // gate kp group (8 pairs)
    float4 px[4];
    uint4  pgh[2], pgm[2];

    auto ldg_tile = [&](int t) {
        const size_t kb = (size_t)t * TILE_K;
#pragma unroll
        for (int l = 0; l < 4; l++) {
            int r = pr + l * 16;
            px[l] = *(const float4*)&x[(size_t)(n0 + r) * D_DIM + kb + pq];
        }
        const size_t gb = (size_t)ge * D2 + t * 32 + gq;
        pgh[0] = *(const uint4*)&g_gate_h[gb];
        pgh[1] = *(const uint4*)&g_gate_h[gb + 4];
        pgm[0] = *(const uint4*)&g_gate_m[gb];
        pgm[1] = *(const uint4*)&g_gate_m[gb + 4];
    };
    auto split_store = [&](int buf) {
        unsigned* b = sm + buf * BUF_U32;
#pragma unroll
        for (int l = 0; l < 4; l++) {
            int r = pr + l * 16;
            float4 v = px[l];
            unsigned h0, m0, h1, m1;
            bf16_split2(v.x, v.y, h0, m0);
            bf16_split2(v.z, v.w, h1, m1);
            *(uint2*)&b[XH_OFF + r * 36 + (pq >> 1)] = make_uint2(h0, h1);
            *(uint2*)&b[XM_OFF + r * 36 + (pq >> 1)] = make_uint2(m0, m1);
        }
        *(uint4*)&b[GH_OFF + ge * 36 + gq]     = pgh[0];
        *(uint4*)&b[GH_OFF + ge * 36 + gq + 4] = pgh[1];
        *(uint4*)&b[GM_OFF + ge * 36 + gq]     = pgm[0];
        *(uint4*)&b[GM_OFF + ge * 36 + gq + 4] = pgm[1];
    };

    // ---- prologue: tile0 -> buf0; tile1 -> regs --------------------------
    ldg_tile(0);
    split_store(0);
    ldg_tile(1);
    if (tid == 0) s_nf = 0;
    __syncthreads();

    for (int t = 0; t < NT; t++) {
        const int cur = t & 1;
        const unsigned* b = sm + cur * BUF_U32;

        if (t < NT - 1) split_store(1 - cur);

        {   // interleaved zero-fill (streaming, evict-first)
            float4* z = zb + t * ZTILE4;
#pragma unroll
            for (int j = 0; j < 20; j++) __stcs(&z[j * 256], z4);
        }

        if (t < NT - 2) ldg_tile(t + 2);

        // MMA: 4 k16 steps x 4 n-tiles x 4 products
#pragma unroll
        for (int ks = 0; ks < 4; ks++) {
            const unsigned kb = ks * 8;
            unsigned ah0 = b[XH_OFF + abase + kb];
            unsigned ah1 = b[XH_OFF + abase + kb + 288];
            unsigned ah2 = b[XH_OFF + abase + kb + 4];
            unsigned ah3 = b[XH_OFF + abase + kb + 292];
            unsigned am0 = b[XM_OFF + abase + kb];
            unsigned am1 = b[XM_OFF + abase + kb + 288];
            unsigned am2 = b[XM_OFF + abase + kb + 4];
            unsigned am3 = b[XM_OFF + abase + kb + 292];
#pragma unroll
            for (int nt = 0; nt < 4; nt++) {
                const unsigned cb = (unsigned)((wn + nt * 8 + g) * 36 + t4 + kb);
                unsigned bh0 = b[GH_OFF + cb];
                unsigned bh1 = b[GH_OFF + cb + 4];
                unsigned bm0 = b[GM_OFF + cb];
                unsigned bm1 = b[GM_OFF + cb + 4];
                MMA_BF16(c[nt][0], c[nt][1], c[nt][2], c[nt][3],
                         ah0, ah1, ah2, ah3, bh0, bh1);
                MMA_BF16(c[nt][0], c[nt][1], c[nt][2], c[nt][3],
                         ah0, ah1, ah2, ah3, bm0, bm1);
                MMA_BF16(c[nt][0], c[nt][1], c[nt][2], c[nt][3],
                         am0, am1, am2, am3, bh0, bh1);
                MMA_BF16(c[nt][0], c[nt][1], c[nt][2], c[nt][3],
                         am0, am1, am2, am3, bm0, bm1);
            }
        }
        __syncthreads();
    }

    // ---- stage logits into smem overlay [64][68] -------------------------
    float* lg = (float*)sm;
    {
        const int r0 = wm + g;
#pragma unroll
        for (int nt = 0; nt < 4; nt++) {
            int col = wn + nt * 8 + 2 * t4;
            lg[r0 * LG_S + col]           = c[nt][0];
            lg[r0 * LG_S + col + 1]       = c[nt][1];
            lg[(r0 + 8) * LG_S + col]     = c[nt][2];
            lg[(r0 + 8) * LG_S + col + 1] = c[nt][3];
        }
    }
    __syncthreads();

    // ---- per-token softmax stats + top-3-guarded top-2 -------------------
    if (tid < 64) {
        const int t = tid;
        float m = -INFINITY;
#pragma unroll
        for (int e = 0; e < N_EXP; e++) m = fmaxf(m, lg[t * LG_S + e]);
        float s = 0.0f;
#pragma unroll
        for (int e = 0; e < N_EXP; e++) s += expf(lg[t * LG_S + e] - m);
        float inv = 1.0f / s;
        smax[t] = m;
        sinv[t] = inv;

        float v1 = -INFINITY, v2 = -INFINITY, v3 = -INFINITY;
        int i1 = 0, i2 = 0;
#pragma unroll
        for (int e = 0; e < N_EXP; e++) {
            float v = lg[t * LG_S + e];
            if (v > v1)      { v3 = v2; v2 = v1; i2 = i1; v1 = v; i1 = e; }
            else if (v > v2) { v3 = v2; v2 = v; i2 = e; }
            else if (v > v3) { v3 = v; }
        }
        float p1 = expf(v1 - m) * inv;
        float p2 = expf(v2 - m) * inv;
        float r = 1.0f / (p1 + p2);
        int n = n0 + t;
        g_top_idx8[2 * n]     = (unsigned char)i1;
        g_top_idx8[2 * n + 1] = (unsigned char)i2;
        g_top_w[2 * n]     = p1 * r;
        g_top_w[2 * n + 1] = p2 * r;
        if (v2 - v3 < 1e-3f) {           // near-tie at the 2/3 boundary
            int p = atomicAdd(&s_nf, 1);
            s_list[p] = t;
        }
    }
    __syncthreads();

    // ---- exact fp32 recompute for near-tie tokens (rare) -----------------
    {
        int nf = s_nf;
        for (int f = 0; f < nf; f++) {
            int t = s_list[f];
            int e = tid & 63, q = tid >> 6;           // 4 chunks of 1024 k
            const float4* xr = (const float4*)&x[(size_t)(n0 + t) * D_DIM + q * 1024];
            const float4* gr = (const float4*)&gate_w[(size_t)e * D_DIM + q * 1024];
            float s = 0.0f;
            for (int kk = 0; kk < 256; kk++) {
                float4 a = xr[kk], w = gr[kk];
                s += a.x * w.x + a.y * w.y + a.z * w.z + a.w * w.w;
            }
            part[q][e] = s;
            __syncthreads();
            if (tid < 64)
                exlg[tid] = part[0][tid] + part[1][tid] + part[2][tid] + part[3][tid];
            __syncthreads();
            if (tid == 0) {
                float v1 = -INFINITY, v2 = -INFINITY;
                int i1 = 0, i2 = 0;
                for (int e2 = 0; e2 < N_EXP; e2++) {
                    float v = exlg[e2];
                    if (v > v1) { v2 = v1; i2 = i1; v1 = v; i1 = e2; }
                    else if (v > v2) { v2 = v; i2 = e2; }
                }
                float m = smax[t], inv = sinv[t];
                float p1 = expf(v1 - m) * inv;
                float p2 = expf(v2 - m) * inv;
                float r = 1.0f / (p1 + p2);
                int n = n0 + t;
                g_top_idx8[2 * n]     = (unsigned char)i1;
                g_top_idx8[2 * n + 1] = (unsigned char)i2;
                g_top_w[2 * n]     = p1 * r;
                g_top_w[2 * n + 1] = p2 * r;
            }
            __syncthreads();
        }
    }

    // ---- probs: 1 token x 16 experts per thread; keep p in lg ------------
    {
        int t = tid >> 2;
        int e0 = (tid & 3) * 16;
        float m = smax[t], inv = sinv[t];
        float buf[16];
#pragma unroll
        for (int i = 0; i < 16; i++)
            buf[i] = expf(lg[t * LG_S + e0 + i] - m) * inv;
        float4* dst = (float4*)&probs_out[(size_t)(n0 + t) * N_EXP + e0];
#pragma unroll
        for (int q = 0; q < 4; q++)
            dst[q] = make_float4(buf[4 * q], buf[4 * q + 1],
                                 buf[4 * q + 2], buf[4 * q + 3]);
#pragma unroll
        for (int i = 0; i < 16; i++) lg[t * LG_S + e0 + i] = buf[i];
    }
    __syncthreads();

    if (tid < 64) {
        const int e = tid;
        float s = 0.0f;
#pragma unroll
        for (int t = 0; t < 64; t++) s += lg[t * LG_S + e];
        atomicAdd(&g_psum[e], s);
    }
}

// ---------------- scan + scatter + loss (one block per expert) ------------
__global__ void __launch_bounds__(256)
k_scan_scatter_loss(float* __restrict__ out_mask,
                    float* __restrict__ out_comb,
                    float* __restrict__ out_loss) {
    __shared__ int warp_sums[8];
    const int e = blockIdx.x;
    const int tid = threadIdx.x;
    const int lane = tid & 31;
    const int wid = tid >> 5;

    uint4 wv[4];
#pragma unroll
    for (int i = 0; i < 4; i++)
        wv[i] = ((const uint4*)g_top_idx8)[tid * 4 + i];
    unsigned w[16];
#pragma unroll
    for (int i = 0; i < 4; i++) {
        w[4 * i + 0] = wv[i].x; w[4 * i + 1] = wv[i].y;
        w[4 * i + 2] = wv[i].z; w[4 * i + 3] = wv[i].w;
    }

    const unsigned eb = (unsigned)e * 0x01010101u;
    int local = 0;
#pragma unroll
    for (int i = 0; i < 16; i++) local += __popc(__vcmpeq4(w[i], eb));
    local >>= 3;

    int incl = local;
#pragma unroll
    for (int off = 1; off < 32; off <<= 1) {
        int v = __shfl_up_sync(0xffffffffu, incl, off);
        if (lane >= off) incl += v;
    }
    if (lane == 31) warp_sums[wid] = incl;
    __syncthreads();
    int base = 0;
#pragma unroll
    for (int j = 0; j < 8; j++) base += (j < wid) ? warp_sums[j] : 0;

    int c = base + incl - local;   // exclusive prefix for this thread
#pragma unroll
    for (int i = 0; i < 16; i++) {
        unsigned word = w[i];
#pragma unroll
        for (int b = 0; b < 4; b++) {
            if (((word >> (8 * b)) & 0xffu) == (unsigned)e) {
                if (c < CAP) {
                    int fi = tid * 64 + i * 4 + b;
                    size_t off = (size_t)(fi >> 1) * (N_EXP * CAP)
                               + (size_t)e * CAP + c;
                    out_mask[off] = 1.0f;
                    out_comb[off] = g_top_w[fi];
                }
                c++;
            }
        }
    }
    if (tid == 255) {
        int total = base + incl;
        float f = (float)total / (float)FLAT;
        float p = g_psum[e] / (float)N_TOK;
        atomicAdd(out_loss, 0.01f * (float)N_EXP * f * p);
    }
}

// ---------------- launch (single stream) -----------------------------------
extern "C" void kernel_launch(void* const* d_in, const int* in_sizes, int n_in,
                              void* d_out, int out_size) {
    const float* x      = (const float*)d_in[0];
    const float* gate_w = (const float*)d_in[1];
    float* out = (float*)d_out;

    float* out_mask  = out;                                   // N*E*C
    float* out_comb  = out + (size_t)NEC;                     // N*E*C
    float* out_probs = out + (size_t)2 * NEC;                 // N*E
    float* out_loss  = out + (size_t)2 * NEC + (size_t)N_TOK * N_EXP;

    cudaFuncSetAttribute(k_gemm,
        cudaFuncAttributeMaxDynamicSharedMemorySize, SMEM_BYTES);

    k_prep<<<(N_EXP * D2) / 256, 256>>>(gate_w, out_loss);
    k_gemm<<<GEMM_GRID, 256, SMEM_BYTES>>>(x, gate_w, out_probs, (float4*)out);
    k_scan_scatter_loss<<<N_EXP, 256>>>(out_mask, out_comb, out_loss);
}